// round 1
// baseline (speedup 1.0000x reference)
#include <cuda_runtime.h>
#include <math.h>

#define Bsz 2
#define Lq  2048
#define Dm  256
#define Hh  8
#define hd  32
#define CH  128
#define NCH 16
#define BHn (Bsz*Hh)
#define EPSf 1e-5f

// ---- scratch (device globals; no allocations allowed) ----
__device__ float g_q[BHn*Lq*hd];      // [bh][l][d]  raw q
__device__ float g_k[BHn*Lq*hd];      // raw k -> overwritten with normalized k
__device__ float g_v[BHn*Lq*hd];      // raw v -> overwritten with normalized v
__device__ float g_sim[BHn*Lq];
__device__ float g_gate[BHn*Lq];
__device__ float g_Sc[BHn*NCH*hd*hd]; // per-chunk state sums
__device__ float g_Sp[BHn*NCH*hd*hd]; // exclusive prefix states
__device__ float g_gsum[BHn*NCH];
__device__ float g_gp[BHn*NCH];
__device__ float g_mc[BHn*NCH];
__device__ float g_mp[BHn*NCH];
__device__ float g_scC[BHn*NCH];
__device__ float g_sp[BHn*NCH];
__device__ float g_ctx[Bsz*Lq*Dm];    // [b][l][h*32+e]

__device__ __forceinline__ float warpSum(float v) {
    #pragma unroll
    for (int o = 16; o; o >>= 1) v += __shfl_xor_sync(0xffffffffu, v, o);
    return v;
}

// ============================================================
// K1: fused QKV projection GEMM.  y = x @ W^T + b  (NT GEMM)
// 64x64 tile, 256 threads, 4x4 microtile, BK=16, fp32
// grid (4096/64, 12): blockIdx.y/4 selects q/k/v, %4 selects col-block
// ============================================================
__global__ void k_qkv(const float* __restrict__ x,
                      const float* __restrict__ wq, const float* __restrict__ bq,
                      const float* __restrict__ wk, const float* __restrict__ bk,
                      const float* __restrict__ wv, const float* __restrict__ bv)
{
    __shared__ float As[16*68];
    __shared__ float Bs[16*68];
    const int t    = threadIdx.x;
    const int m0   = blockIdx.x * 64;
    const int mat  = blockIdx.y >> 2;
    const int n0   = (blockIdx.y & 3) * 64;
    const float* W    = (mat == 0) ? wq : ((mat == 1) ? wk : wv);
    const float* bias = (mat == 0) ? bq : ((mat == 1) ? bk : bv);
    const int arow = t >> 2, aq = t & 3;
    const int tx = t & 15, ty = t >> 4;

    float acc[4][4] = {};
    for (int k0 = 0; k0 < 256; k0 += 16) {
        float4 a4 = *(const float4*)(x + (m0 + arow) * 256 + k0 + aq * 4);
        float4 b4 = *(const float4*)(W + (n0 + arow) * 256 + k0 + aq * 4);
        As[(aq*4+0)*68 + arow] = a4.x; As[(aq*4+1)*68 + arow] = a4.y;
        As[(aq*4+2)*68 + arow] = a4.z; As[(aq*4+3)*68 + arow] = a4.w;
        Bs[(aq*4+0)*68 + arow] = b4.x; Bs[(aq*4+1)*68 + arow] = b4.y;
        Bs[(aq*4+2)*68 + arow] = b4.z; Bs[(aq*4+3)*68 + arow] = b4.w;
        __syncthreads();
        #pragma unroll
        for (int kk = 0; kk < 16; kk++) {
            float4 av  = *(float4*)&As[kk*68 + tx*4];
            float4 bb  = *(float4*)&Bs[kk*68 + ty*4];
            acc[0][0] += av.x*bb.x; acc[0][1] += av.x*bb.y; acc[0][2] += av.x*bb.z; acc[0][3] += av.x*bb.w;
            acc[1][0] += av.y*bb.x; acc[1][1] += av.y*bb.y; acc[1][2] += av.y*bb.z; acc[1][3] += av.y*bb.w;
            acc[2][0] += av.z*bb.x; acc[2][1] += av.z*bb.y; acc[2][2] += av.z*bb.z; acc[2][3] += av.z*bb.w;
            acc[3][0] += av.w*bb.x; acc[3][1] += av.w*bb.y; acc[3][2] += av.w*bb.z; acc[3][3] += av.w*bb.w;
        }
        __syncthreads();
    }
    float* dst = (mat == 0) ? g_q : ((mat == 1) ? g_k : g_v);
    #pragma unroll
    for (int i = 0; i < 4; i++) {
        int m = m0 + tx*4 + i;
        int b = m >> 11, l = m & 2047;
        #pragma unroll
        for (int j = 0; j < 4; j++) {
            int o = n0 + ty*4 + j;
            float yv = acc[i][j] + bias[o];
            int hidx = o >> 5, d = o & 31;
            dst[((b*Hh + hidx)*Lq + l)*hd + d] = yv;
        }
    }
}

// ============================================================
// K2: per-position preprocess. one warp = one position (32 lanes = 32 dims)
//   sim = (q.k)*qscale[h]; normalize k,v; gate = relu(v^T M k)^2 + EPS
//   M[h] = kv_norm_scale[h] ⊙ wg (exact application of kv_norm_scale in gate)
// grid: BHn * (Lq/256) = 128 blocks, 256 threads
// ============================================================
__global__ void k_prep(const float* __restrict__ wg, const float* __restrict__ wgb,
                       const float* __restrict__ kvs, const float* __restrict__ qks)
{
    __shared__ float Ms[32*33];
    const int tid  = threadIdx.x;
    const int bh   = blockIdx.x >> 3;
    const int lblk = blockIdx.x & 7;
    const int h    = bh & 7;
    for (int idx = tid; idx < 1024; idx += 256) {
        int d = idx >> 5, e = idx & 31;
        Ms[d*33 + e] = kvs[h*1024 + idx] * wg[idx];
    }
    __syncthreads();
    const float qscale = qks[h];
    const float wb0    = wgb[0];
    const int warp = tid >> 5, lane = tid & 31;
    for (int jj = 0; jj < 32; jj++) {
        int l    = lblk*256 + warp*32 + jj;
        int base = (bh*Lq + l)*hd + lane;
        float qd = g_q[base], kd = g_k[base], vd = g_v[base];
        float sim = warpSum(qd*kd) * qscale;
        float kn  = sqrtf(warpSum(kd*kd));
        float kh  = kd / fmaxf(kn, 1e-12f);
        float vn  = sqrtf(warpSum(vd*vd));
        float vh  = vd / fmaxf(vn, 1e-12f);
        float td = 0.f;
        #pragma unroll
        for (int e = 0; e < 32; e++)
            td += Ms[lane*33 + e] * __shfl_sync(0xffffffffu, kh, e);
        float logit = warpSum(vh*td) + wb0;
        float r = fmaxf(logit, 0.f);
        float gate = r*r + EPSf;
        g_k[base] = kh;
        g_v[base] = vh;
        if (lane == 0) { g_sim[bh*Lq + l] = sim; g_gate[bh*Lq + l] = gate; }
    }
}

// ============================================================
// K3: per-chunk sums: S_chunk = sum g_i v_i k_i^T, g_sum, (m_c, s_c)
// grid: BHn*NCH = 256 blocks, 256 threads (thread owns 4 S elems)
// ============================================================
__global__ void k_chunk()
{
    __shared__ float Ks[CH*hd];
    __shared__ float Vs[CH*hd];
    __shared__ float gs[CH];
    __shared__ float sims[CH];
    const int tid = threadIdx.x;
    const int bx  = blockIdx.x;
    const int bh  = bx >> 4, c = bx & 15;
    const int gb  = (bh*Lq + c*CH)*hd;
    for (int idx = tid*4; idx < CH*hd; idx += 1024) {
        *(float4*)&Ks[idx] = *(const float4*)&g_k[gb + idx];
        *(float4*)&Vs[idx] = *(const float4*)&g_v[gb + idx];
    }
    if (tid < CH) {
        gs[tid]   = g_gate[bh*Lq + c*CH + tid];
        sims[tid] = g_sim [bh*Lq + c*CH + tid];
    }
    __syncthreads();
    const int d = tid >> 3, e0 = (tid & 7) * 4;
    float4 acc = {0.f, 0.f, 0.f, 0.f};
    for (int i = 0; i < CH; i++) {
        float cfv = gs[i] * Vs[i*hd + d];
        float4 k4 = *(float4*)&Ks[i*hd + e0];
        acc.x += cfv*k4.x; acc.y += cfv*k4.y; acc.z += cfv*k4.z; acc.w += cfv*k4.w;
    }
    *(float4*)&g_Sc[bx*1024 + tid*4] = acc;
    if (tid < 32) {
        float m = -1e30f;
        #pragma unroll
        for (int k = 0; k < 4; k++) m = fmaxf(m, sims[tid + 32*k]);
        #pragma unroll
        for (int o = 16; o; o >>= 1) m = fmaxf(m, __shfl_xor_sync(0xffffffffu, m, o));
        float s = 0.f, gsum = 0.f;
        #pragma unroll
        for (int k = 0; k < 4; k++) { s += __expf(sims[tid + 32*k] - m); gsum += gs[tid + 32*k]; }
        s = warpSum(s); gsum = warpSum(gsum);
        if (tid == 0) { g_mc[bx] = m; g_scC[bx] = s; g_gsum[bx] = gsum; }
    }
}

// ============================================================
// K4: exclusive prefix over 16 chunks per (b,h). grid 16 blocks.
// ============================================================
__global__ void k_prefix()
{
    const int bh = blockIdx.x, tid = threadIdx.x;
    float4 acc = {0.f, 0.f, 0.f, 0.f};
    for (int c = 0; c < NCH; c++) {
        int idx = (bh*NCH + c)*1024 + tid*4;
        *(float4*)&g_Sp[idx] = acc;
        float4 v = *(const float4*)&g_Sc[idx];
        acc.x += v.x; acc.y += v.y; acc.z += v.z; acc.w += v.w;
    }
    if (tid == 0) {
        float m = -1e30f, s = 0.f, ga = 0.f;
        for (int c = 0; c < NCH; c++) {
            int i = bh*NCH + c;
            g_mp[i] = m; g_sp[i] = s; g_gp[i] = ga;
            float mc = g_mc[i], sc = g_scC[i];
            float mn = fmaxf(m, mc);
            s = s*__expf(m - mn) + sc*__expf(mc - mn);
            m = mn;
            ga += g_gsum[i];
        }
    }
}

// ============================================================
// K5: intra-chunk outputs. grid BHn*NCH = 256 blocks, 256 threads (8 warps)
//   intra scalar scans (Hillis-Steele) combined with chunk prefix,
//   then per-row: ctxt = w/(g+eps) * [ q^T S_prev + sum_{i<=l} g_i (q.v_i) k_i ]
// ============================================================
__global__ void k_intra()
{
    __shared__ float Vs[CH*33];
    __shared__ float Ks[CH*33];
    __shared__ float Sps[hd*hd];
    __shared__ float cf[8*CH];
    __shared__ float mA[CH], sA[CH], gA[CH], simA[CH], rawg[CH], ws[CH], dinv[CH];
    const int tid = threadIdx.x;
    const int bx  = blockIdx.x;
    const int bh  = bx >> 4, c = bx & 15;
    const int b   = bh >> 3, h = bh & 7;
    const int gb  = (bh*Lq + c*CH)*hd;

    for (int idx = tid; idx < CH*hd; idx += 256) {
        int i = idx >> 5, d = idx & 31;
        Vs[i*33 + d] = g_v[gb + idx];
        Ks[i*33 + d] = g_k[gb + idx];
    }
    { int idx = tid*4; *(float4*)&Sps[idx] = *(const float4*)&g_Sp[bx*1024 + idx]; }
    if (tid < CH) {
        float sv = g_sim [bh*Lq + c*CH + tid];
        float gv = g_gate[bh*Lq + c*CH + tid];
        mA[tid] = sv; simA[tid] = sv; sA[tid] = 1.f; gA[tid] = gv; rawg[tid] = gv;
    }
    __syncthreads();

    // inclusive scans within chunk
    for (int off = 1; off < CH; off <<= 1) {
        float m2 = 0.f, s2 = 0.f, g2 = 0.f;
        bool act = (tid < CH) && (tid >= off);
        if (act) { m2 = mA[tid-off]; s2 = sA[tid-off]; g2 = gA[tid-off]; }
        __syncthreads();
        if (act) {
            float mn = fmaxf(mA[tid], m2);
            sA[tid] = sA[tid]*__expf(mA[tid] - mn) + s2*__expf(m2 - mn);
            mA[tid] = mn;
            gA[tid] += g2;
        }
        __syncthreads();
    }
    if (tid < CH) {
        float mp = g_mp[bx], sp = g_sp[bx], gp = g_gp[bx];
        float mn = fmaxf(mp, mA[tid]);
        float st = sp*__expf(mp - mn) + sA[tid]*__expf(mA[tid] - mn);
        float sw = __expf(simA[tid] - mn) / (st + EPSf);
        ws[tid]   = 1.f + sw / (1.f + __expf(-sw));   // 1 + silu(sw)
        dinv[tid] = 1.f / (gp + gA[tid] + EPSf);
    }
    __syncthreads();

    const int warp = tid >> 5, lane = tid & 31;
    for (int r = warp; r < CH; r += 8) {
        float q[32];
        const float* qg = g_q + gb + r*hd;
        #pragma unroll
        for (int d4 = 0; d4 < 32; d4 += 4) {
            float4 q4 = *(const float4*)(qg + d4);
            q[d4] = q4.x; q[d4+1] = q4.y; q[d4+2] = q4.z; q[d4+3] = q4.w;
        }
        const int ng = (r >> 5) + 1;
        for (int g4 = 0; g4 < ng; g4++) {
            int i = lane + 32*g4;
            float a = 0.f;
            #pragma unroll
            for (int d = 0; d < 32; d++) a += q[d] * Vs[i*33 + d];
            cf[warp*CH + i] = (i <= r) ? rawg[i]*a : 0.f;
        }
        __syncwarp();
        float y = 0.f;
        const int e = lane;
        #pragma unroll 4
        for (int i = 0; i <= r; i++) y += cf[warp*CH + i] * Ks[i*33 + e];
        #pragma unroll
        for (int d = 0; d < 32; d++) y += q[d] * Sps[d*hd + e];
        y *= ws[r] * dinv[r];
        g_ctx[(b*Lq + c*CH + r)*Dm + h*hd + e] = y;
        __syncwarp();
    }
}

// ============================================================
// K6: output projection: out = ctx @ wo^T + bo
// ============================================================
__global__ void k_out(const float* __restrict__ wo, const float* __restrict__ bo,
                      float* __restrict__ out)
{
    __shared__ float As[16*68];
    __shared__ float Bs[16*68];
    const int t  = threadIdx.x;
    const int m0 = blockIdx.x * 64;
    const int n0 = blockIdx.y * 64;
    const int arow = t >> 2, aq = t & 3;
    const int tx = t & 15, ty = t >> 4;

    float acc[4][4] = {};
    for (int k0 = 0; k0 < 256; k0 += 16) {
        float4 a4 = *(const float4*)(g_ctx + (m0 + arow)*256 + k0 + aq*4);
        float4 b4 = *(const float4*)(wo    + (n0 + arow)*256 + k0 + aq*4);
        As[(aq*4+0)*68 + arow] = a4.x; As[(aq*4+1)*68 + arow] = a4.y;
        As[(aq*4+2)*68 + arow] = a4.z; As[(aq*4+3)*68 + arow] = a4.w;
        Bs[(aq*4+0)*68 + arow] = b4.x; Bs[(aq*4+1)*68 + arow] = b4.y;
        Bs[(aq*4+2)*68 + arow] = b4.z; Bs[(aq*4+3)*68 + arow] = b4.w;
        __syncthreads();
        #pragma unroll
        for (int kk = 0; kk < 16; kk++) {
            float4 av = *(float4*)&As[kk*68 + tx*4];
            float4 bb = *(float4*)&Bs[kk*68 + ty*4];
            acc[0][0] += av.x*bb.x; acc[0][1] += av.x*bb.y; acc[0][2] += av.x*bb.z; acc[0][3] += av.x*bb.w;
            acc[1][0] += av.y*bb.x; acc[1][1] += av.y*bb.y; acc[1][2] += av.y*bb.z; acc[1][3] += av.y*bb.w;
            acc[2][0] += av.z*bb.x; acc[2][1] += av.z*bb.y; acc[2][2] += av.z*bb.z; acc[2][3] += av.z*bb.w;
            acc[3][0] += av.w*bb.x; acc[3][1] += av.w*bb.y; acc[3][2] += av.w*bb.z; acc[3][3] += av.w*bb.w;
        }
        __syncthreads();
    }
    #pragma unroll
    for (int i = 0; i < 4; i++) {
        int m = m0 + tx*4 + i;
        #pragma unroll
        for (int j = 0; j < 4; j++) {
            int o = n0 + ty*4 + j;
            out[m*256 + o] = acc[i][j] + bo[o];
        }
    }
}

// ============================================================
extern "C" void kernel_launch(void* const* d_in, const int* in_sizes, int n_in,
                              void* d_out, int out_size)
{
    const float* x   = (const float*)d_in[0];
    const float* wq  = (const float*)d_in[1];
    const float* bq  = (const float*)d_in[2];
    const float* wk  = (const float*)d_in[3];
    const float* bk  = (const float*)d_in[4];
    const float* wv  = (const float*)d_in[5];
    const float* bv  = (const float*)d_in[6];
    const float* wo  = (const float*)d_in[7];
    const float* bo  = (const float*)d_in[8];
    const float* wg  = (const float*)d_in[9];
    const float* wgb = (const float*)d_in[10];
    const float* kvs = (const float*)d_in[11];
    const float* qks = (const float*)d_in[12];
    float* out = (float*)d_out;

    k_qkv  <<<dim3(64, 12), 256>>>(x, wq, bq, wk, bk, wv, bv);
    k_prep <<<128, 256>>>(wg, wgb, kvs, qks);
    k_chunk<<<256, 256>>>();
    k_prefix<<<16, 256>>>();
    k_intra<<<256, 256>>>();
    k_out  <<<dim3(64, 4), 256>>>(wo, bo, out);
}

// round 2
// speedup vs baseline: 1.5190x; 1.5190x over previous
#include <cuda_runtime.h>
#include <mma.h>
#include <math.h>

using namespace nvcuda;

#define Bsz 2
#define Lq  2048
#define Dm  256
#define Hh  8
#define hd  32
#define CH  128
#define NCH 16
#define BHn (Bsz*Hh)
#define EPSf 1e-5f

// ---- scratch (device globals; no allocations allowed) ----
__device__ float g_q[BHn*Lq*hd];      // [bh][l][d]  raw q
__device__ float g_k[BHn*Lq*hd];      // raw k -> overwritten with normalized k
__device__ float g_v[BHn*Lq*hd];      // raw v -> overwritten with normalized v
__device__ float g_sim[BHn*Lq];
__device__ float g_gate[BHn*Lq];
__device__ float g_Sc[BHn*NCH*hd*hd]; // per-chunk state sums
__device__ float g_gsum[BHn*NCH];
__device__ float g_mc[BHn*NCH];
__device__ float g_scC[BHn*NCH];
__device__ float g_ctx[Bsz*Lq*Dm];    // [b][l][h*32+e]

__device__ __forceinline__ float warpSum(float v) {
    #pragma unroll
    for (int o = 16; o; o >>= 1) v += __shfl_xor_sync(0xffffffffu, v, o);
    return v;
}

// ============================================================
// K1: fused QKV projection GEMM via tf32 tensor cores.
//   y = x @ W^T + b   (x: [4096,256], W: [256,256] row-major [out,in])
// BM=128, BN=64, BK=32. 256 threads = 8 warps (4x2), warp tile 32x32.
// grid: (4096/128=32, 12): blockIdx.y/4 selects q/k/v, %4 selects n-block
// ============================================================
#define LDA 40
__global__ void k_qkv(const float* __restrict__ x,
                      const float* __restrict__ wq, const float* __restrict__ bq,
                      const float* __restrict__ wk, const float* __restrict__ bk,
                      const float* __restrict__ wv, const float* __restrict__ bv)
{
    __shared__ float buf[8192];                       // 32KB, reused As/Bs -> Cs
    float* As = buf;                                  // [128][LDA]
    float* Bs = buf + 128*LDA;                        // [64][LDA]  (Bs[n][k])
    const int t    = threadIdx.x;
    const int m0   = blockIdx.x * 128;
    const int mat  = blockIdx.y >> 2;
    const int n0   = (blockIdx.y & 3) * 64;
    const float* W    = (mat == 0) ? wq : ((mat == 1) ? wk : wv);
    const float* bias = (mat == 0) ? bq : ((mat == 1) ? bk : bv);

    const int warp = t >> 5;
    const int wm = warp >> 1, wn = warp & 1;          // 4x2 warp grid

    wmma::fragment<wmma::accumulator, 16, 16, 8, float> c[2][2];
    #pragma unroll
    for (int i = 0; i < 2; i++)
        #pragma unroll
        for (int j = 0; j < 2; j++) wmma::fill_fragment(c[i][j], 0.0f);

    const int lrow = t >> 3, lcol = (t & 7) * 4;
    for (int k0 = 0; k0 < 256; k0 += 32) {
        // load A tile 128x32 (4 passes of 32 rows)
        #pragma unroll
        for (int r = 0; r < 4; r++) {
            float4 a4 = *(const float4*)(x + (m0 + lrow + r*32)*256 + k0 + lcol);
            float* d = &As[(lrow + r*32)*LDA + lcol];
            d[0] = wmma::__float_to_tf32(a4.x); d[1] = wmma::__float_to_tf32(a4.y);
            d[2] = wmma::__float_to_tf32(a4.z); d[3] = wmma::__float_to_tf32(a4.w);
        }
        // load B tile 64x32 (2 passes)
        #pragma unroll
        for (int r = 0; r < 2; r++) {
            float4 b4 = *(const float4*)(W + (n0 + lrow + r*32)*256 + k0 + lcol);
            float* d = &Bs[(lrow + r*32)*LDA + lcol];
            d[0] = wmma::__float_to_tf32(b4.x); d[1] = wmma::__float_to_tf32(b4.y);
            d[2] = wmma::__float_to_tf32(b4.z); d[3] = wmma::__float_to_tf32(b4.w);
        }
        __syncthreads();
        #pragma unroll
        for (int kk = 0; kk < 4; kk++) {
            wmma::fragment<wmma::matrix_a, 16, 16, 8, wmma::precision::tf32, wmma::row_major> a[2];
            wmma::fragment<wmma::matrix_b, 16, 16, 8, wmma::precision::tf32, wmma::col_major> b[2];
            #pragma unroll
            for (int i = 0; i < 2; i++)
                wmma::load_matrix_sync(a[i], &As[(wm*32 + i*16)*LDA + kk*8], LDA);
            #pragma unroll
            for (int j = 0; j < 2; j++)
                wmma::load_matrix_sync(b[j], &Bs[(wn*32 + j*16)*LDA + kk*8], LDA);
            #pragma unroll
            for (int i = 0; i < 2; i++)
                #pragma unroll
                for (int j = 0; j < 2; j++)
                    wmma::mma_sync(c[i][j], a[i], b[j], c[i][j]);
        }
        __syncthreads();
    }
    // write accumulators to smem then scatter with reshape
    float* Cs = buf;                                  // [128][64]
    #pragma unroll
    for (int i = 0; i < 2; i++)
        #pragma unroll
        for (int j = 0; j < 2; j++)
            wmma::store_matrix_sync(&Cs[(wm*32 + i*16)*64 + wn*32 + j*16], c[i][j], 64, wmma::mem_row_major);
    __syncthreads();
    float* dst = (mat == 0) ? g_q : ((mat == 1) ? g_k : g_v);
    for (int idx = t; idx < 128*64; idx += 256) {
        int row = idx >> 6, col = idx & 63;
        int m = m0 + row;
        int b = m >> 11, l = m & 2047;
        int o = n0 + col;
        int hidx = o >> 5, d = o & 31;
        dst[((b*Hh + hidx)*Lq + l)*hd + d] = Cs[idx] + bias[o];
    }
}

// ============================================================
// K2: fused per-position preprocess + per-chunk sums.
// grid: BHn*NCH = 256 blocks, 256 threads (8 warps, 16 positions each)
//   sim = (q.k)*qscale; normalize k,v; gate = relu(v^T M k)^2 + EPS
//   then S_chunk = sum g_i v_i k_i^T, g_sum, (m_c, s_c)
// ============================================================
__global__ void k_prepchunk(const float* __restrict__ wg, const float* __restrict__ wgb,
                            const float* __restrict__ kvs, const float* __restrict__ qks)
{
    __shared__ float Ks[CH*hd];     // stride 32 (float4-friendly)
    __shared__ float Vs[CH*hd];
    __shared__ float Ms[32*33];
    __shared__ float gs[CH], sims[CH];
    const int tid = threadIdx.x;
    const int bx  = blockIdx.x;
    const int bh  = bx >> 4, c = bx & 15;
    const int h   = bh & 7;
    for (int idx = tid; idx < 1024; idx += 256) {
        int d = idx >> 5, e = idx & 31;
        Ms[d*33 + e] = kvs[h*1024 + idx] * wg[idx];
    }
    __syncthreads();
    const float qscale = qks[h];
    const float wb0    = wgb[0];
    const int warp = tid >> 5, lane = tid & 31;
    for (int jj = 0; jj < 16; jj++) {
        int pos  = warp*16 + jj;
        int l    = c*CH + pos;
        int base = (bh*Lq + l)*hd + lane;
        float qd = g_q[base], kd = g_k[base], vd = g_v[base];
        float sim = warpSum(qd*kd) * qscale;
        float kh  = kd / fmaxf(sqrtf(warpSum(kd*kd)), 1e-12f);
        float vh  = vd / fmaxf(sqrtf(warpSum(vd*vd)), 1e-12f);
        Ks[pos*hd + lane] = kh;
        Vs[pos*hd + lane] = vh;
        g_k[base] = kh;
        g_v[base] = vh;
        __syncwarp();
        float td = 0.f;
        #pragma unroll
        for (int e = 0; e < 32; e++)
            td += Ms[lane*33 + e] * Ks[pos*hd + e];
        float logit = warpSum(vh*td) + wb0;
        float r = fmaxf(logit, 0.f);
        float gate = r*r + EPSf;
        if (lane == 0) {
            gs[pos] = gate; sims[pos] = sim;
            g_gate[bh*Lq + l] = gate; g_sim[bh*Lq + l] = sim;
        }
    }
    __syncthreads();
    // per-chunk outer-product sum
    const int d = tid >> 3, e0 = (tid & 7) * 4;
    float4 acc = {0.f, 0.f, 0.f, 0.f};
    for (int i = 0; i < CH; i++) {
        float cfv = gs[i] * Vs[i*hd + d];
        float4 k4 = *(float4*)&Ks[i*hd + e0];
        acc.x += cfv*k4.x; acc.y += cfv*k4.y; acc.z += cfv*k4.z; acc.w += cfv*k4.w;
    }
    *(float4*)&g_Sc[bx*1024 + tid*4] = acc;
    if (tid < 32) {
        float m = -1e30f;
        #pragma unroll
        for (int k = 0; k < 4; k++) m = fmaxf(m, sims[tid + 32*k]);
        #pragma unroll
        for (int o = 16; o; o >>= 1) m = fmaxf(m, __shfl_xor_sync(0xffffffffu, m, o));
        float s = 0.f, gsum = 0.f;
        #pragma unroll
        for (int k = 0; k < 4; k++) { s += __expf(sims[tid + 32*k] - m); gsum += gs[tid + 32*k]; }
        s = warpSum(s); gsum = warpSum(gsum);
        if (tid == 0) { g_mc[bx] = m; g_scC[bx] = s; g_gsum[bx] = gsum; }
    }
}

// ============================================================
// K3: intra-chunk outputs (with inlined chunk prefix).
// grid BHn*NCH = 256 blocks, 256 threads (8 warps)
// ============================================================
__global__ void k_intra()
{
    __shared__ float Vs[CH*33];
    __shared__ float Ks[CH*33];
    __shared__ float Sps[hd*hd];
    __shared__ float cf[8*CH];
    __shared__ float mA[CH], sA[CH], gA[CH], simA[CH], rawg[CH], ws[CH], dinv[CH];
    __shared__ float s_mp, s_sp, s_gp;
    const int tid = threadIdx.x;
    const int bx  = blockIdx.x;
    const int bh  = bx >> 4, c = bx & 15;
    const int b   = bh >> 3, h = bh & 7;
    const int gb  = (bh*Lq + c*CH)*hd;

    // exclusive prefix of chunk states (sum of chunks < c)
    {
        int idx = tid*4;
        float4 a = {0.f, 0.f, 0.f, 0.f};
        for (int cc = 0; cc < c; cc++) {
            float4 v = *(const float4*)&g_Sc[(bh*NCH + cc)*1024 + idx];
            a.x += v.x; a.y += v.y; a.z += v.z; a.w += v.w;
        }
        *(float4*)&Sps[idx] = a;
    }
    if (tid == 0) {
        float m = -1e30f, s = 0.f, ga = 0.f;
        for (int cc = 0; cc < c; cc++) {
            int i = bh*NCH + cc;
            float mc = g_mc[i], sc = g_scC[i];
            float mn = fmaxf(m, mc);
            s = s*__expf(m - mn) + sc*__expf(mc - mn);
            m = mn;
            ga += g_gsum[i];
        }
        s_mp = m; s_sp = s; s_gp = ga;
    }

    for (int idx = tid; idx < CH*hd; idx += 256) {
        int i = idx >> 5, d = idx & 31;
        Vs[i*33 + d] = g_v[gb + idx];
        Ks[i*33 + d] = g_k[gb + idx];
    }
    if (tid < CH) {
        float sv = g_sim [bh*Lq + c*CH + tid];
        float gv = g_gate[bh*Lq + c*CH + tid];
        mA[tid] = sv; simA[tid] = sv; sA[tid] = 1.f; gA[tid] = gv; rawg[tid] = gv;
    }
    __syncthreads();

    // inclusive scans within chunk
    for (int off = 1; off < CH; off <<= 1) {
        float m2 = 0.f, s2 = 0.f, g2 = 0.f;
        bool act = (tid < CH) && (tid >= off);
        if (act) { m2 = mA[tid-off]; s2 = sA[tid-off]; g2 = gA[tid-off]; }
        __syncthreads();
        if (act) {
            float mn = fmaxf(mA[tid], m2);
            sA[tid] = sA[tid]*__expf(mA[tid] - mn) + s2*__expf(m2 - mn);
            mA[tid] = mn;
            gA[tid] += g2;
        }
        __syncthreads();
    }
    if (tid < CH) {
        float mp = s_mp, sp = s_sp, gp = s_gp;
        float mn = fmaxf(mp, mA[tid]);
        float st = sp*__expf(mp - mn) + sA[tid]*__expf(mA[tid] - mn);
        float sw = __expf(simA[tid] - mn) / (st + EPSf);
        ws[tid]   = 1.f + sw / (1.f + __expf(-sw));   // 1 + silu(sw)
        dinv[tid] = 1.f / (gp + gA[tid] + EPSf);
    }
    __syncthreads();

    const int warp = tid >> 5, lane = tid & 31;
    for (int r = warp; r < CH; r += 8) {
        float q[32];
        const float* qg = g_q + gb + r*hd;
        #pragma unroll
        for (int d4 = 0; d4 < 32; d4 += 4) {
            float4 q4 = *(const float4*)(qg + d4);
            q[d4] = q4.x; q[d4+1] = q4.y; q[d4+2] = q4.z; q[d4+3] = q4.w;
        }
        const int ng = (r >> 5) + 1;
        for (int g4 = 0; g4 < ng; g4++) {
            int i = lane + 32*g4;
            float a = 0.f;
            #pragma unroll
            for (int d = 0; d < 32; d++) a += q[d] * Vs[i*33 + d];
            cf[warp*CH + i] = (i <= r) ? rawg[i]*a : 0.f;
        }
        __syncwarp();
        float y = 0.f;
        const int e = lane;
        #pragma unroll 4
        for (int i = 0; i <= r; i++) y += cf[warp*CH + i] * Ks[i*33 + e];
        #pragma unroll
        for (int d = 0; d < 32; d++) y += q[d] * Sps[d*hd + e];
        y *= ws[r] * dinv[r];
        g_ctx[(b*Lq + c*CH + r)*Dm + h*hd + e] = y;
        __syncwarp();
    }
}

// ============================================================
// K4: output projection via tf32 tensor cores: out = ctx @ wo^T + bo
// ============================================================
__global__ void k_out(const float* __restrict__ wo, const float* __restrict__ bo,
                      float* __restrict__ out)
{
    __shared__ float buf[8192];
    float* As = buf;
    float* Bs = buf + 128*LDA;
    const int t  = threadIdx.x;
    const int m0 = blockIdx.x * 128;
    const int n0 = blockIdx.y * 64;
    const int warp = t >> 5;
    const int wm = warp >> 1, wn = warp & 1;

    wmma::fragment<wmma::accumulator, 16, 16, 8, float> c[2][2];
    #pragma unroll
    for (int i = 0; i < 2; i++)
        #pragma unroll
        for (int j = 0; j < 2; j++) wmma::fill_fragment(c[i][j], 0.0f);

    const int lrow = t >> 3, lcol = (t & 7) * 4;
    for (int k0 = 0; k0 < 256; k0 += 32) {
        #pragma unroll
        for (int r = 0; r < 4; r++) {
            float4 a4 = *(const float4*)(g_ctx + (m0 + lrow + r*32)*256 + k0 + lcol);
            float* d = &As[(lrow + r*32)*LDA + lcol];
            d[0] = wmma::__float_to_tf32(a4.x); d[1] = wmma::__float_to_tf32(a4.y);
            d[2] = wmma::__float_to_tf32(a4.z); d[3] = wmma::__float_to_tf32(a4.w);
        }
        #pragma unroll
        for (int r = 0; r < 2; r++) {
            float4 b4 = *(const float4*)(wo + (n0 + lrow + r*32)*256 + k0 + lcol);
            float* d = &Bs[(lrow + r*32)*LDA + lcol];
            d[0] = wmma::__float_to_tf32(b4.x); d[1] = wmma::__float_to_tf32(b4.y);
            d[2] = wmma::__float_to_tf32(b4.z); d[3] = wmma::__float_to_tf32(b4.w);
        }
        __syncthreads();
        #pragma unroll
        for (int kk = 0; kk < 4; kk++) {
            wmma::fragment<wmma::matrix_a, 16, 16, 8, wmma::precision::tf32, wmma::row_major> a[2];
            wmma::fragment<wmma::matrix_b, 16, 16, 8, wmma::precision::tf32, wmma::col_major> b[2];
            #pragma unroll
            for (int i = 0; i < 2; i++)
                wmma::load_matrix_sync(a[i], &As[(wm*32 + i*16)*LDA + kk*8], LDA);
            #pragma unroll
            for (int j = 0; j < 2; j++)
                wmma::load_matrix_sync(b[j], &Bs[(wn*32 + j*16)*LDA + kk*8], LDA);
            #pragma unroll
            for (int i = 0; i < 2; i++)
                #pragma unroll
                for (int j = 0; j < 2; j++)
                    wmma::mma_sync(c[i][j], a[i], b[j], c[i][j]);
        }
        __syncthreads();
    }
    float* Cs = buf;
    #pragma unroll
    for (int i = 0; i < 2; i++)
        #pragma unroll
        for (int j = 0; j < 2; j++)
            wmma::store_matrix_sync(&Cs[(wm*32 + i*16)*64 + wn*32 + j*16], c[i][j], 64, wmma::mem_row_major);
    __syncthreads();
    for (int idx = t; idx < 128*64; idx += 256) {
        int row = idx >> 6, col = idx & 63;
        int o = n0 + col;
        out[(m0 + row)*256 + o] = Cs[idx] + bo[o];
    }
}

// ============================================================
extern "C" void kernel_launch(void* const* d_in, const int* in_sizes, int n_in,
                              void* d_out, int out_size)
{
    const float* x   = (const float*)d_in[0];
    const float* wq  = (const float*)d_in[1];
    const float* bq  = (const float*)d_in[2];
    const float* wk  = (const float*)d_in[3];
    const float* bk  = (const float*)d_in[4];
    const float* wv  = (const float*)d_in[5];
    const float* bv  = (const float*)d_in[6];
    const float* wo  = (const float*)d_in[7];
    const float* bo  = (const float*)d_in[8];
    const float* wg  = (const float*)d_in[9];
    const float* wgb = (const float*)d_in[10];
    const float* kvs = (const float*)d_in[11];
    const float* qks = (const float*)d_in[12];
    float* out = (float*)d_out;

    k_qkv      <<<dim3(32, 12), 256>>>(x, wq, bq, wk, bk, wv, bv);
    k_prepchunk<<<256, 256>>>(wg, wgb, kvs, qks);
    k_intra    <<<256, 256>>>();
    k_out      <<<dim3(32, 4), 256>>>(wo, bo, out);
}